// round 16
// baseline (speedup 1.0000x reference)
#include <cuda_runtime.h>

typedef unsigned long long u64;
typedef unsigned int u32;

__device__ __forceinline__ float ex2f(float x) {
    float y; asm("ex2.approx.ftz.f32 %0, %1;" : "=f"(y) : "f"(x)); return y;
}
__device__ __forceinline__ u32 tf32c(float x) {
    u32 r; asm("cvt.rna.tf32.f32 %0, %1;" : "=r"(r) : "f"(x)); return r;
}
__device__ __forceinline__ void mma8(float *d, const u32 *a, u32 b0, u32 b1) {
    asm("mma.sync.aligned.m16n8k8.row.col.f32.tf32.tf32.f32 "
        "{%0,%1,%2,%3}, {%4,%5,%6,%7}, {%8,%9}, {%0,%1,%2,%3};"
        : "+f"(d[0]), "+f"(d[1]), "+f"(d[2]), "+f"(d[3])
        : "r"(a[0]), "r"(a[1]), "r"(a[2]), "r"(a[3]), "r"(b0), "r"(b1));
}
__device__ __forceinline__ void cpa16(void* s, const void* g) {
    unsigned sa = (unsigned)__cvta_generic_to_shared(s);
    asm volatile("cp.async.ca.shared.global [%0], [%1], 16;" :: "r"(sa), "l"(g));
}
__device__ __forceinline__ void cpcommit() { asm volatile("cp.async.commit_group;"); }
__device__ __forceinline__ void cpwait1() { asm volatile("cp.async.wait_group 1;"); }
__device__ __forceinline__ void cpwait0() { asm volatile("cp.async.wait_group 0;"); }

#define LOG2E 1.4426950408889634f

// ---------------- scratch ----------------
__device__ float g_qT[2 * 4 * 4096 * 32];      // q * scale * log2e
__device__ float g_y3a[2 * 256 * 256];
__device__ float g_y3b[2 * 256 * 1024];
// K/V pre-split into tf32 hi/lo (bit patterns stored as float)
__device__ float g_K1h[2 * 4 * 512 * 32],  g_K1l[2 * 4 * 512 * 32];
__device__ float g_V1h[2 * 4 * 512 * 32],  g_V1l[2 * 4 * 512 * 32];
__device__ float g_K2h[2 * 4 * 2048 * 32], g_K2l[2 * 4 * 2048 * 32];
__device__ float g_V2h[2 * 4 * 2048 * 32], g_V2l[2 * 4 * 2048 * 32];
__device__ float g_cr1[2 * 64 * 512];          // rpe * log2e
__device__ float g_cr2[2 * 64 * 2048];
__device__ int   g_rbase[4096];
__device__ float g_rw[4096 * 4];
// flash partials: [cb][t<8][n][4], cb = (b*4+h)*nc + chunk ; nc1=2, nc2=8
__device__ float g_pO1[2 * 4 * 2 * 8 * 4096 * 4];
__device__ float g_pO2[2 * 4 * 8 * 8 * 4096 * 4];
__device__ float g_pm1[2 * 4 * 2 * 4096];
__device__ float g_ps1[2 * 4 * 2 * 4096];
__device__ float g_pm2[2 * 4 * 8 * 4096];
__device__ float g_ps2[2 * 4 * 8 * 4096];

// Keys cubic a=-0.5, jax.image.resize semantics (drop OOB taps, renormalize).
__device__ __forceinline__ void cubic4(float sample, int size, int &base, float *w) {
    int t0 = (int)floorf(sample) - 1;
    float ws[4]; float sum = 0.f;
#pragma unroll
    for (int j = 0; j < 4; j++) {
        int t = t0 + j;
        float xd = fabsf(sample - (float)t);
        float wv;
        if (xd <= 1.f)      wv = ((1.5f * xd - 2.5f) * xd) * xd + 1.f;
        else if (xd < 2.f)  wv = ((-0.5f * xd + 2.5f) * xd - 4.f) * xd + 2.f;
        else                wv = 0.f;
        if (t < 0 || t >= size) wv = 0.f;
        ws[j] = wv; sum += wv;
    }
    float inv = 1.f / sum;
    int nb = t0 < 0 ? 0 : (t0 > size - 4 ? size - 4 : t0);
    base = nb;
    w[0] = w[1] = w[2] = w[3] = 0.f;
#pragma unroll
    for (int j = 0; j < 4; j++) {
        int t = t0 + j;
        if (t >= 0 && t < size) w[t - nb] = ws[j] * inv;
    }
}

__global__ void rowtab_k() {
    int n = blockIdx.x * 256 + threadIdx.x;
    if (n >= 4096) return;
    float sample = (n + 0.5f) * 0.015625f - 0.5f;
    int base; float w[4];
    cubic4(sample, 64, base, w);
    g_rbase[n] = base;
#pragma unroll
    for (int j = 0; j < 4; j++) g_rw[n * 4 + j] = w[j];
}

__global__ void colres_k(const float * __restrict__ rpe, int Lc, int branch) {
    int idx = blockIdx.x * blockDim.x + threadIdx.x;
    if (idx >= 2 * 64 * Lc) return;
    int l = idx % Lc;
    int r = (idx / Lc) & 63;
    int b = idx / (Lc * 64);
    float sample = (l + 0.5f) * (64.f / (float)Lc) - 0.5f;
    int base; float w[4];
    cubic4(sample, 64, base, w);
    const float *row = rpe + ((size_t)(b * 2 + branch) * 64 + r) * 64;
    float v = w[0]*row[base] + w[1]*row[base+1] + w[2]*row[base+2] + w[3]*row[base+3];
    (branch ? g_cr2 : g_cr1)[((size_t)b * 64 + r) * Lc + l] = v * LOG2E;
}

// fused 1x1-conv GEMMs: u<512 q | 512..640 kv br1 | 640..1152 kv br2
__global__ void __launch_bounds__(128) gemm_k(const float * __restrict__ xin,
                                              const float * __restrict__ qw,
                                              const float * __restrict__ qb,
                                              const float * __restrict__ kvw,
                                              const float * __restrict__ kvb) {
    int u = blockIdx.x;
    int mode, nt, ct, b;
    if (u < 512)      { mode = 0; nt = u & 127; ct = (u >> 7) & 1; b = u >> 8; }
    else if (u < 640) { int v = u - 512; mode = 1; nt = v & 7;  ct = (v >> 3) & 7; b = v >> 6; }
    else              { int v = u - 640; mode = 2; nt = v & 31; ct = (v >> 5) & 7; b = v >> 8; }
    const float *X; int HW;
    if (mode == 0)      { X = xin;   HW = 4096; }
    else if (mode == 1) { X = g_y3a; HW = 256;  }
    else                { X = g_y3b; HW = 1024; }
    const float *W    = mode ? kvw : qw;
    const float *bias = mode ? kvb : qb;
    __shared__ float Xs[64 * 32];
    __shared__ float Ws[64 * 65];
    int tid = threadIdx.x, tn = tid & 7, tc = tid >> 3;
    float acc[4][4] = {};
    const float *xb = X + (size_t)b * 256 * HW + nt * 32;
    for (int cc = 0; cc < 4; cc++) {
        __syncthreads();
        for (int i = tid; i < 2048; i += 128)
            Xs[i] = xb[(size_t)(cc * 64 + (i >> 5)) * HW + (i & 31)];
        for (int i = tid; i < 4096; i += 128) {
            int co = i >> 6, k = i & 63;
            Ws[co * 65 + k] = W[(size_t)(ct * 64 + co) * 256 + cc * 64 + k];
        }
        __syncthreads();
#pragma unroll 4
        for (int ci = 0; ci < 64; ci++) {
            float4 xv = *(const float4*)&Xs[ci * 32 + tn * 4];
            float xa[4] = {xv.x, xv.y, xv.z, xv.w};
#pragma unroll
            for (int k2 = 0; k2 < 4; k2++) {
                float wv = Ws[(tc * 4 + k2) * 65 + ci];
#pragma unroll
                for (int j = 0; j < 4; j++) acc[k2][j] = fmaf(wv, xa[j], acc[k2][j]);
            }
        }
    }
    if (mode == 0) {
        const float SCALE = 0.17677669529663687f * LOG2E;
#pragma unroll
        for (int k2 = 0; k2 < 4; k2++) {
            int co = ct * 64 + tc * 4 + k2;
            float bv = bias[co];
            int h = co >> 5, d = co & 31;
#pragma unroll
            for (int j = 0; j < 4; j++) {
                int n = nt * 32 + tn * 4 + j;
                g_qT[((size_t)(b * 4 + h) * 4096 + n) * 32 + d] = (acc[k2][j] + bv) * SCALE;
            }
        }
    } else {
        int L = 2 * HW;
        float *KH = (mode == 2) ? g_K2h : g_K1h;
        float *KL = (mode == 2) ? g_K2l : g_K1l;
        float *VH = (mode == 2) ? g_V2h : g_V1h;
        float *VL = (mode == 2) ? g_V2l : g_V1l;
#pragma unroll
        for (int k2 = 0; k2 < 4; k2++) {
            int co = ct * 64 + tc * 4 + k2;
            float bv = bias[co];
            int cm = co & 255, h = cm >> 6, d = (cm & 63) >> 1, e = cm & 1;
            float *dH = (co < 256) ? KH : VH;
            float *dL = (co < 256) ? KL : VL;
#pragma unroll
            for (int j = 0; j < 4; j++) {
                int s = nt * 32 + tn * 4 + j;
                float val = acc[k2][j] + bv;
                u32 hi = tf32c(val);
                u32 lo = tf32c(val - __uint_as_float(hi));
                size_t idx = ((size_t)(b * 4 + h) * L + e * HW + s) * 32 + d;
                dH[idx] = __uint_as_float(hi);
                dL[idx] = __uint_as_float(lo);
            }
        }
    }
}

// fused per-plane body: dwconv+bn1+relu, pw*bn2, local3x3+bias+residual
template <int K, int S, int P, int HO, int BR>
__device__ __forceinline__ void plane_body(int bidx,
                                           const float * __restrict__ x,
                                           const float * __restrict__ dww,
                                           const float * __restrict__ bn1,
                                           const float * __restrict__ pww,
                                           const float * __restrict__ bn2,
                                           const float * __restrict__ lw,
                                           const float * __restrict__ lb,
                                           float *xs, float *ys, float *wk) {
    int b = bidx >> 8, c = bidx & 255;
    int tid = threadIdx.x;
    const float *xp = x + (size_t)(b * 256 + c) * 4096;
    for (int i = tid; i < 4096; i += 256) xs[i] = xp[i];
    if (tid < K * K) wk[tid] = dww[c * K * K + tid];
    float a1 = bn1[c] * rsqrtf(bn1[768 + c] + 1e-5f);
    float c1 = bn1[256 + c] - bn1[512 + c] * a1;
    float s2 = bn2[c] * rsqrtf(bn2[768 + c] + 1e-5f);
    float A2 = pww[c] * s2;
    float B2 = bn2[256 + c] - bn2[512 + c] * s2;
    __syncthreads();
    for (int o = tid; o < HO * HO; o += 256) {
        int oy = o / HO, ox = o - oy * HO;
        float acc = 0.f;
#pragma unroll
        for (int ky = 0; ky < K; ky++) {
            int iy = oy * S - P + ky;
            if (iy < 0 || iy > 63) continue;
#pragma unroll
            for (int kx = 0; kx < K; kx++) {
                int ix = ox * S - P + kx;
                if (ix >= 0 && ix <= 63) acc = fmaf(wk[ky * K + kx], xs[iy * 64 + ix], acc);
            }
        }
        float y1 = fmaxf(fmaf(acc, a1, c1), 0.f);
        ys[o] = fmaf(y1, A2, B2);
    }
    __syncthreads();
    float l9[9];
#pragma unroll
    for (int t = 0; t < 9; t++) l9[t] = lw[c * 9 + t];
    float lbv = lb[c];
    float *outp = (BR ? g_y3b : g_y3a) + (size_t)(b * 256 + c) * (HO * HO);
    for (int o = tid; o < HO * HO; o += 256) {
        int oy = o / HO, ox = o - oy * HO;
        float acc = lbv;
#pragma unroll
        for (int ky = 0; ky < 3; ky++) {
            int iy = oy - 1 + ky;
            if (iy < 0 || iy >= HO) continue;
#pragma unroll
            for (int kx = 0; kx < 3; kx++) {
                int ix = ox - 1 + kx;
                if (ix >= 0 && ix < HO) acc = fmaf(l9[ky * 3 + kx], ys[iy * HO + ix], acc);
            }
        }
        outp[o] = acc + ys[o];
    }
}

__global__ void __launch_bounds__(256) planes_k(const float * __restrict__ x,
                                                const float * __restrict__ dw1,
                                                const float * __restrict__ bn11,
                                                const float * __restrict__ pw1,
                                                const float * __restrict__ bn12,
                                                const float * __restrict__ dw2,
                                                const float * __restrict__ bn21,
                                                const float * __restrict__ pw2,
                                                const float * __restrict__ bn22,
                                                const float * __restrict__ lw,
                                                const float * __restrict__ lb) {
    __shared__ float xs[4096];
    __shared__ float ys[1024];
    __shared__ float wk[49];
    if (blockIdx.x < 512)
        plane_body<7, 4, 3, 16, 0>(blockIdx.x, x, dw1, bn11, pw1, bn12, lw, lb, xs, ys, wk);
    else
        plane_body<5, 2, 2, 32, 1>(blockIdx.x - 512, x, dw2, bn21, pw2, bn22, lw, lb, xs, ys, wk);
}

// -------- tf32 tensor-core flash attention (3xTF32 both GEMMs, pre-split K/V) --------
// CTA = 128 thr = 4 warps sharing tiles; warp = 32 query rows.
// grid 2560: u<2048 br2 (8 chunks of 256 l); else br1 (2 chunks of 256 l).
__global__ void __launch_bounds__(128) attn_k() {
    int u = blockIdx.x;
    int b, h, br, ntile, chunk;
    if (u < 2048) { br = 1; b = u >> 10; int r = u & 1023; h = r >> 8;
                    int r2 = r & 255; ntile = r2 >> 3; chunk = r2 & 7; }
    else { int v = u - 2048; br = 0; b = v >> 8; int r = v & 255; h = r >> 6;
           int r2 = r & 63; ntile = r2 >> 1; chunk = r2 & 1; }
    int L = br ? 2048 : 512;
    const float *KHp = br ? g_K2h : g_K1h;
    const float *KLp = br ? g_K2l : g_K1l;
    const float *VHp = br ? g_V2h : g_V1h;
    const float *VLp = br ? g_V2l : g_V1l;
    const float *cr  = br ? g_cr2 : g_cr1;

    int tid = threadIdx.x, w = tid >> 5, lane = tid & 31;
    int g = lane >> 2, t = lane & 3;
    int n0 = ntile * 128;
    int n0w = n0 + w * 32;

    __shared__ __align__(16) float KSH[2][16][36], KSL[2][16][36];
    __shared__ __align__(16) float VSH[2][16][36], VSL[2][16][36];
    __shared__ __align__(16) float CRS[2][6][16];
    __shared__ float PS[4][32][17];

    // q A-fragments split hi/lo (3xTF32); loop-invariant
    u32 qfh[2][4][4], qfl[2][4][4];
    const float *qbase = g_qT + (size_t)(b * 4 + h) * 4096 * 32;
#pragma unroll
    for (int mt = 0; mt < 2; mt++)
#pragma unroll
        for (int kt = 0; kt < 4; kt++) {
            int r0r = n0w + mt * 16 + g, c0c = kt * 8 + t;
            float v0 = qbase[(size_t)r0r * 32 + c0c];
            float v1 = qbase[(size_t)(r0r + 8) * 32 + c0c];
            float v2 = qbase[(size_t)r0r * 32 + c0c + 4];
            float v3 = qbase[(size_t)(r0r + 8) * 32 + c0c + 4];
            qfh[mt][kt][0] = tf32c(v0); qfl[mt][kt][0] = tf32c(v0 - __uint_as_float(qfh[mt][kt][0]));
            qfh[mt][kt][1] = tf32c(v1); qfl[mt][kt][1] = tf32c(v1 - __uint_as_float(qfh[mt][kt][1]));
            qfh[mt][kt][2] = tf32c(v2); qfl[mt][kt][2] = tf32c(v2 - __uint_as_float(qfh[mt][kt][2]));
            qfh[mt][kt][3] = tf32c(v3); qfl[mt][kt][3] = tf32c(v3 - __uint_as_float(qfh[mt][kt][3]));
        }

    // per-row bicubic weights (4 rows per thread: i = mt*2 + half)
    int r0 = g_rbase[n0];
    float wv[4][4]; int rr[4];
#pragma unroll
    for (int i = 0; i < 4; i++) {
        int ni = n0w + (i >> 1) * 16 + (i & 1) * 8 + g;
        rr[i] = g_rbase[ni] - r0;
#pragma unroll
        for (int j = 0; j < 4; j++) wv[i][j] = g_rw[ni * 4 + j];
    }

    size_t hb = (size_t)(b * 4 + h) * L * 32;
    const float *crb = cr + (size_t)b * 64 * L;
    int l0base = chunk * 256;

    float of[2][4][4] = {};
    float m[4], sum[4];
#pragma unroll
    for (int i = 0; i < 4; i++) { m[i] = -1e30f; sum[i] = 0.f; }

    auto stage = [&](int buf, int l0) {
        int row = tid >> 3, c16 = tid & 7;
        size_t off = hb + (size_t)(l0 + row) * 32 + c16 * 4;
        cpa16(&KSH[buf][row][c16 * 4], KHp + off);
        cpa16(&KSL[buf][row][c16 * 4], KLp + off);
        cpa16(&VSH[buf][row][c16 * 4], VHp + off);
        cpa16(&VSL[buf][row][c16 * 4], VLp + off);
        if (tid < 24) {
            int rrow = tid >> 2, c4 = tid & 3;
            int rc = r0 + rrow; if (rc > 63) rc = 63;
            cpa16(&CRS[buf][rrow][c4 * 4], crb + (size_t)rc * L + l0 + c4 * 4);
        }
        cpcommit();
    };

    stage(0, l0base);
    for (int ti = 0; ti < 16; ti++) {
        int cur = ti & 1;
        if (ti < 15) { stage(cur ^ 1, l0base + (ti + 1) * 16); cpwait1(); }
        else cpwait0();
        __syncthreads();

        // S accum seeded with rpe
        float sf[2][2][4];
#pragma unroll
        for (int i = 0; i < 4; i++) {
            int mt = i >> 1, hf = i & 1;
#pragma unroll
            for (int nt = 0; nt < 2; nt++)
#pragma unroll
                for (int d = 0; d < 2; d++) {
                    int col = nt * 8 + 2 * t + d;
                    float v = wv[i][0] * CRS[cur][rr[i]][col]
                            + wv[i][1] * CRS[cur][rr[i] + 1][col]
                            + wv[i][2] * CRS[cur][rr[i] + 2][col]
                            + wv[i][3] * CRS[cur][rr[i] + 3][col];
                    sf[mt][nt][hf * 2 + d] = v;
                }
        }
        // S = q @ K^T + rpe   (3xTF32: hi*hi + lo*hi + hi*lo)
#pragma unroll
        for (int nt = 0; nt < 2; nt++)
#pragma unroll
            for (int kt = 0; kt < 4; kt++) {
                u32 b0h = __float_as_uint(KSH[cur][nt * 8 + g][kt * 8 + t]);
                u32 b1h = __float_as_uint(KSH[cur][nt * 8 + g][kt * 8 + t + 4]);
                u32 b0l = __float_as_uint(KSL[cur][nt * 8 + g][kt * 8 + t]);
                u32 b1l = __float_as_uint(KSL[cur][nt * 8 + g][kt * 8 + t + 4]);
                mma8(sf[0][nt], qfh[0][kt], b0h, b1h);
                mma8(sf[1][nt], qfh[1][kt], b0h, b1h);
                mma8(sf[0][nt], qfl[0][kt], b0h, b1h);
                mma8(sf[1][nt], qfl[1][kt], b0h, b1h);
                mma8(sf[0][nt], qfh[0][kt], b0l, b1l);
                mma8(sf[1][nt], qfh[1][kt], b0l, b1l);
            }
        // online softmax per row; write fp32 P to PS (sum uses SAME p)
#pragma unroll
        for (int i = 0; i < 4; i++) {
            int mt = i >> 1, hf = i & 1;
            float a = fmaxf(fmaxf(sf[mt][0][2 * hf], sf[mt][0][2 * hf + 1]),
                            fmaxf(sf[mt][1][2 * hf], sf[mt][1][2 * hf + 1]));
            a = fmaxf(a, __shfl_xor_sync(0xffffffffu, a, 1));
            a = fmaxf(a, __shfl_xor_sync(0xffffffffu, a, 2));
            float nm = fmaxf(m[i], a);
            float f = ex2f(m[i] - nm);
            m[i] = nm; sum[i] *= f;
#pragma unroll
            for (int nt = 0; nt < 4; nt++) {
                of[mt][nt][2 * hf] *= f;
                of[mt][nt][2 * hf + 1] *= f;
            }
            int prow = mt * 16 + hf * 8 + g;
#pragma unroll
            for (int nt = 0; nt < 2; nt++)
#pragma unroll
                for (int d = 0; d < 2; d++) {
                    float p = ex2f(sf[mt][nt][2 * hf + d] - nm);
                    sum[i] += p;
                    PS[w][prow][nt * 8 + 2 * t + d] = p;
                }
        }
        __syncwarp();
        // O += P @ V   (3xTF32: ph*vh + pl*vh + ph*vl)
        u32 pah[2][2][4], pal[2][2][4];
#pragma unroll
        for (int mt = 0; mt < 2; mt++)
#pragma unroll
            for (int kt = 0; kt < 2; kt++) {
                float f0 = PS[w][mt * 16 + g][kt * 8 + t];
                float f1 = PS[w][mt * 16 + g + 8][kt * 8 + t];
                float f2 = PS[w][mt * 16 + g][kt * 8 + t + 4];
                float f3 = PS[w][mt * 16 + g + 8][kt * 8 + t + 4];
                pah[mt][kt][0] = tf32c(f0); pal[mt][kt][0] = tf32c(f0 - __uint_as_float(pah[mt][kt][0]));
                pah[mt][kt][1] = tf32c(f1); pal[mt][kt][1] = tf32c(f1 - __uint_as_float(pah[mt][kt][1]));
                pah[mt][kt][2] = tf32c(f2); pal[mt][kt][2] = tf32c(f2 - __uint_as_float(pah[mt][kt][2]));
                pah[mt][kt][3] = tf32c(f3); pal[mt][kt][3] = tf32c(f3 - __uint_as_float(pah[mt][kt][3]));
            }
#pragma unroll
        for (int kt = 0; kt < 2; kt++)
#pragma unroll
            for (int nt = 0; nt < 4; nt++) {
                u32 b0h = __float_as_uint(VSH[cur][kt * 8 + t][nt * 8 + g]);
                u32 b1h = __float_as_uint(VSH[cur][kt * 8 + t + 4][nt * 8 + g]);
                u32 b0l = __float_as_uint(VSL[cur][kt * 8 + t][nt * 8 + g]);
                u32 b1l = __float_as_uint(VSL[cur][kt * 8 + t + 4][nt * 8 + g]);
                mma8(of[0][nt], pah[0][kt], b0h, b1h);
                mma8(of[1][nt], pah[1][kt], b0h, b1h);
                mma8(of[0][nt], pal[0][kt], b0h, b1h);
                mma8(of[1][nt], pal[1][kt], b0h, b1h);
                mma8(of[0][nt], pah[0][kt], b0l, b1l);
                mma8(of[1][nt], pah[1][kt], b0l, b1l);
            }
        __syncthreads();   // anti-WAR: all warps done with buf `cur` before next prefetch into it
    }

    // epilogue: partials
    int nc = br ? 8 : 2;
    float *pO = br ? g_pO2 : g_pO1;
    float *pm = br ? g_pm2 : g_pm1;
    float *ps = br ? g_ps2 : g_ps1;
    size_t cb = (size_t)(b * 4 + h) * nc + chunk;
#pragma unroll
    for (int i = 0; i < 4; i++) {
        sum[i] += __shfl_xor_sync(0xffffffffu, sum[i], 1);
        sum[i] += __shfl_xor_sync(0xffffffffu, sum[i], 2);
    }
    if (t == 0) {
#pragma unroll
        for (int i = 0; i < 4; i++) {
            int ni = n0w + (i >> 1) * 16 + (i & 1) * 8 + g;
            pm[cb * 4096 + ni] = m[i];
            ps[cb * 4096 + ni] = sum[i];
        }
    }
#pragma unroll
    for (int mt = 0; mt < 2; mt++)
#pragma unroll
        for (int nt = 0; nt < 4; nt++)
#pragma unroll
            for (int k = 0; k < 4; k++) {
                int ni = n0w + mt * 16 + (k >> 1) * 8 + g;
                int d = nt * 8 + 2 * t + (k & 1);
                pO[((cb * 8 + (d >> 2)) * 4096 + ni) * 4 + (d & 3)] = of[mt][nt][k];
            }
}

// merge flash partials -> output (exp2 domain)
__global__ void __launch_bounds__(256) merge_k(float * __restrict__ out) {
    int idx = blockIdx.x * 256 + threadIdx.x;       // 65536
    int n = idx & 4095, h = (idx >> 12) & 3, br = (idx >> 14) & 1, b = idx >> 15;
    int nc = br ? 8 : 2;
    const float *pm = br ? g_pm2 : g_pm1;
    const float *ps = br ? g_ps2 : g_ps1;
    const float4 *pO = (const float4*)(br ? g_pO2 : g_pO1);
    size_t base = (size_t)(b * 4 + h) * nc;
    float M = -1e30f;
    for (int c = 0; c < nc; c++) M = fmaxf(M, pm[(base + c) * 4096 + n]);
    float S = 0.f;
    float4 acc[8] = {};
    for (int c = 0; c < nc; c++) {
        float w = ex2f(pm[(base + c) * 4096 + n] - M);
        S += w * ps[(base + c) * 4096 + n];
#pragma unroll
        for (int t = 0; t < 8; t++) {
            float4 v = pO[((base + c) * 8 + t) * 4096 + n];
            acc[t].x += w * v.x; acc[t].y += w * v.y;
            acc[t].z += w * v.z; acc[t].w += w * v.w;
        }
    }
    float inv = 1.f / S;
    int ny = n >> 6, nx = n & 63;
    float4 *op = (float4*)(out + ((((size_t)b * 256 + h * 64 + ny) * 64 + nx) * 64 + br * 32));
#pragma unroll
    for (int t = 0; t < 8; t++)
        op[t] = make_float4(acc[t].x * inv, acc[t].y * inv, acc[t].z * inv, acc[t].w * inv);
}

extern "C" void kernel_launch(void* const* d_in, const int* in_sizes, int n_in,
                              void* d_out, int out_size) {
    const float *x    = (const float*)d_in[0];
    const float *rpe  = (const float*)d_in[1];
    const float *q_w  = (const float*)d_in[2];
    const float *q_b  = (const float*)d_in[3];
    const float *kv_w = (const float*)d_in[4];
    const float *kv_b = (const float*)d_in[5];
    const float *dw1  = (const float*)d_in[6];
    const float *bn11 = (const float*)d_in[7];
    const float *pw1  = (const float*)d_in[8];
    const float *bn12 = (const float*)d_in[9];
    const float *dw2  = (const float*)d_in[10];
    const float *bn21 = (const float*)d_in[11];
    const float *pw2  = (const float*)d_in[12];
    const float *bn22 = (const float*)d_in[13];
    const float *lw   = (const float*)d_in[14];
    const float *lb   = (const float*)d_in[15];
    float *out = (float*)d_out;

    rowtab_k<<<16, 256>>>();
    colres_k<<<256, 256>>>(rpe, 512, 0);
    colres_k<<<1024, 256>>>(rpe, 2048, 1);
    planes_k<<<1024, 256>>>(x, dw1, bn11, pw1, bn12, dw2, bn21, pw2, bn22, lw, lb);
    gemm_k<<<1152, 128>>>(x, q_w, q_b, kv_w, kv_b);
    attn_k<<<2560, 128>>>();      // launch #6 -> captured by ncu (-s 5 -c 1)
    merge_k<<<256, 256>>>(out);
}

// round 17
// speedup vs baseline: 1.5354x; 1.5354x over previous
#include <cuda_runtime.h>
#include <cuda_fp16.h>

typedef unsigned long long u64;
typedef unsigned int u32;

__device__ __forceinline__ float ex2f(float x) {
    float y; asm("ex2.approx.ftz.f32 %0, %1;" : "=f"(y) : "f"(x)); return y;
}
__device__ __forceinline__ void mma16(float *d, const u32 *a, u32 b0, u32 b1) {
    asm("mma.sync.aligned.m16n8k16.row.col.f32.f16.f16.f32 "
        "{%0,%1,%2,%3}, {%4,%5,%6,%7}, {%8,%9}, {%0,%1,%2,%3};"
        : "+f"(d[0]), "+f"(d[1]), "+f"(d[2]), "+f"(d[3])
        : "r"(a[0]), "r"(a[1]), "r"(a[2]), "r"(a[3]), "r"(b0), "r"(b1));
}
__device__ __forceinline__ void h2split(float a, float b, u32 &hi, u32 &lo) {
    __half2 h = __floats2half2_rn(a, b);
    float ra = a - __half2float(__low2half(h));
    float rb = b - __half2float(__high2half(h));
    __half2 l = __floats2half2_rn(ra, rb);
    hi = *(u32*)&h; lo = *(u32*)&l;
}
__device__ __forceinline__ void cpa16(void* s, const void* g) {
    unsigned sa = (unsigned)__cvta_generic_to_shared(s);
    asm volatile("cp.async.ca.shared.global [%0], [%1], 16;" :: "r"(sa), "l"(g));
}
__device__ __forceinline__ void cpcommit() { asm volatile("cp.async.commit_group;"); }
__device__ __forceinline__ void cpwait1() { asm volatile("cp.async.wait_group 1;"); }
__device__ __forceinline__ void cpwait0() { asm volatile("cp.async.wait_group 0;"); }

#define LOG2E 1.4426950408889634f

// ---------------- scratch ----------------
__device__ float g_qT[2 * 4 * 4096 * 32];      // q * scale * log2e
__device__ float g_y3a[2 * 256 * 256];
__device__ float g_y3b[2 * 256 * 1024];
// K pre-split fp16 hi/lo, layout [bh][l][32]; V transposed [bh][d=32][L]
__device__ __half g_K1h[2 * 4 * 512 * 32],  g_K1l[2 * 4 * 512 * 32];
__device__ __half g_V1h[2 * 4 * 32 * 512],  g_V1l[2 * 4 * 32 * 512];
__device__ __half g_K2h[2 * 4 * 2048 * 32], g_K2l[2 * 4 * 2048 * 32];
__device__ __half g_V2h[2 * 4 * 32 * 2048], g_V2l[2 * 4 * 32 * 2048];
__device__ float g_cr1[2 * 64 * 512];          // rpe * log2e
__device__ float g_cr2[2 * 64 * 2048];
__device__ int   g_rbase[4096];
__device__ float g_rw[4096 * 4];
// flash partials: [cb][t<8][n][4], cb = (b*4+h)*nc + chunk ; nc1=2, nc2=8
__device__ float g_pO1[2 * 4 * 2 * 8 * 4096 * 4];
__device__ float g_pO2[2 * 4 * 8 * 8 * 4096 * 4];
__device__ float g_pm1[2 * 4 * 2 * 4096];
__device__ float g_ps1[2 * 4 * 2 * 4096];
__device__ float g_pm2[2 * 4 * 8 * 4096];
__device__ float g_ps2[2 * 4 * 8 * 4096];

// Keys cubic a=-0.5, jax.image.resize semantics (drop OOB taps, renormalize).
__device__ __forceinline__ void cubic4(float sample, int size, int &base, float *w) {
    int t0 = (int)floorf(sample) - 1;
    float ws[4]; float sum = 0.f;
#pragma unroll
    for (int j = 0; j < 4; j++) {
        int t = t0 + j;
        float xd = fabsf(sample - (float)t);
        float wv;
        if (xd <= 1.f)      wv = ((1.5f * xd - 2.5f) * xd) * xd + 1.f;
        else if (xd < 2.f)  wv = ((-0.5f * xd + 2.5f) * xd - 4.f) * xd + 2.f;
        else                wv = 0.f;
        if (t < 0 || t >= size) wv = 0.f;
        ws[j] = wv; sum += wv;
    }
    float inv = 1.f / sum;
    int nb = t0 < 0 ? 0 : (t0 > size - 4 ? size - 4 : t0);
    base = nb;
    w[0] = w[1] = w[2] = w[3] = 0.f;
#pragma unroll
    for (int j = 0; j < 4; j++) {
        int t = t0 + j;
        if (t >= 0 && t < size) w[t - nb] = ws[j] * inv;
    }
}

__global__ void rowtab_k() {
    int n = blockIdx.x * 256 + threadIdx.x;
    if (n >= 4096) return;
    float sample = (n + 0.5f) * 0.015625f - 0.5f;
    int base; float w[4];
    cubic4(sample, 64, base, w);
    g_rbase[n] = base;
#pragma unroll
    for (int j = 0; j < 4; j++) g_rw[n * 4 + j] = w[j];
}

__global__ void colres_k(const float * __restrict__ rpe, int Lc, int branch) {
    int idx = blockIdx.x * blockDim.x + threadIdx.x;
    if (idx >= 2 * 64 * Lc) return;
    int l = idx % Lc;
    int r = (idx / Lc) & 63;
    int b = idx / (Lc * 64);
    float sample = (l + 0.5f) * (64.f / (float)Lc) - 0.5f;
    int base; float w[4];
    cubic4(sample, 64, base, w);
    const float *row = rpe + ((size_t)(b * 2 + branch) * 64 + r) * 64;
    float v = w[0]*row[base] + w[1]*row[base+1] + w[2]*row[base+2] + w[3]*row[base+3];
    (branch ? g_cr2 : g_cr1)[((size_t)b * 64 + r) * Lc + l] = v * LOG2E;
}

// fused 1x1-conv GEMMs: u<512 q | 512..640 kv br1 | 640..1152 kv br2
__global__ void __launch_bounds__(128) gemm_k(const float * __restrict__ xin,
                                              const float * __restrict__ qw,
                                              const float * __restrict__ qb,
                                              const float * __restrict__ kvw,
                                              const float * __restrict__ kvb) {
    int u = blockIdx.x;
    int mode, nt, ct, b;
    if (u < 512)      { mode = 0; nt = u & 127; ct = (u >> 7) & 1; b = u >> 8; }
    else if (u < 640) { int v = u - 512; mode = 1; nt = v & 7;  ct = (v >> 3) & 7; b = v >> 6; }
    else              { int v = u - 640; mode = 2; nt = v & 31; ct = (v >> 5) & 7; b = v >> 8; }
    const float *X; int HW;
    if (mode == 0)      { X = xin;   HW = 4096; }
    else if (mode == 1) { X = g_y3a; HW = 256;  }
    else                { X = g_y3b; HW = 1024; }
    const float *W    = mode ? kvw : qw;
    const float *bias = mode ? kvb : qb;
    __shared__ float Xs[64 * 32];
    __shared__ float Ws[64 * 65];
    int tid = threadIdx.x, tn = tid & 7, tc = tid >> 3;
    float acc[4][4] = {};
    const float *xb = X + (size_t)b * 256 * HW + nt * 32;
    for (int cc = 0; cc < 4; cc++) {
        __syncthreads();
        for (int i = tid; i < 2048; i += 128)
            Xs[i] = xb[(size_t)(cc * 64 + (i >> 5)) * HW + (i & 31)];
        for (int i = tid; i < 4096; i += 128) {
            int co = i >> 6, k = i & 63;
            Ws[co * 65 + k] = W[(size_t)(ct * 64 + co) * 256 + cc * 64 + k];
        }
        __syncthreads();
#pragma unroll 4
        for (int ci = 0; ci < 64; ci++) {
            float4 xv = *(const float4*)&Xs[ci * 32 + tn * 4];
            float xa[4] = {xv.x, xv.y, xv.z, xv.w};
#pragma unroll
            for (int k2 = 0; k2 < 4; k2++) {
                float wv = Ws[(tc * 4 + k2) * 65 + ci];
#pragma unroll
                for (int j = 0; j < 4; j++) acc[k2][j] = fmaf(wv, xa[j], acc[k2][j]);
            }
        }
    }
    if (mode == 0) {
        const float SCALE = 0.17677669529663687f * LOG2E;
#pragma unroll
        for (int k2 = 0; k2 < 4; k2++) {
            int co = ct * 64 + tc * 4 + k2;
            float bv = bias[co];
            int h = co >> 5, d = co & 31;
#pragma unroll
            for (int j = 0; j < 4; j++) {
                int n = nt * 32 + tn * 4 + j;
                g_qT[((size_t)(b * 4 + h) * 4096 + n) * 32 + d] = (acc[k2][j] + bv) * SCALE;
            }
        }
    } else {
        int L = 2 * HW;
        __half *KH = (mode == 2) ? g_K2h : g_K1h;
        __half *KL = (mode == 2) ? g_K2l : g_K1l;
        __half *VH = (mode == 2) ? g_V2h : g_V1h;
        __half *VL = (mode == 2) ? g_V2l : g_V1l;
#pragma unroll
        for (int k2 = 0; k2 < 4; k2++) {
            int co = ct * 64 + tc * 4 + k2;
            float bv = bias[co];
            int cm = co & 255, h = cm >> 6, d = (cm & 63) >> 1, e = cm & 1;
#pragma unroll
            for (int j = 0; j < 4; j++) {
                int s = nt * 32 + tn * 4 + j;
                float val = acc[k2][j] + bv;
                __half hv = __float2half_rn(val);
                __half lv = __float2half_rn(val - __half2float(hv));
                if (co < 256) {   // K: [bh][l][32]
                    size_t idx = ((size_t)(b * 4 + h) * L + e * HW + s) * 32 + d;
                    KH[idx] = hv; KL[idx] = lv;
                } else {          // V transposed: [bh][d][L]
                    size_t idx = ((size_t)(b * 4 + h) * 32 + d) * L + e * HW + s;
                    VH[idx] = hv; VL[idx] = lv;
                }
            }
        }
    }
}

// fused per-plane body: dwconv+bn1+relu, pw*bn2, local3x3+bias+residual
template <int K, int S, int P, int HO, int BR>
__device__ __forceinline__ void plane_body(int bidx,
                                           const float * __restrict__ x,
                                           const float * __restrict__ dww,
                                           const float * __restrict__ bn1,
                                           const float * __restrict__ pww,
                                           const float * __restrict__ bn2,
                                           const float * __restrict__ lw,
                                           const float * __restrict__ lb,
                                           float *xs, float *ys, float *wk) {
    int b = bidx >> 8, c = bidx & 255;
    int tid = threadIdx.x;
    const float *xp = x + (size_t)(b * 256 + c) * 4096;
    for (int i = tid; i < 4096; i += 256) xs[i] = xp[i];
    if (tid < K * K) wk[tid] = dww[c * K * K + tid];
    float a1 = bn1[c] * rsqrtf(bn1[768 + c] + 1e-5f);
    float c1 = bn1[256 + c] - bn1[512 + c] * a1;
    float s2 = bn2[c] * rsqrtf(bn2[768 + c] + 1e-5f);
    float A2 = pww[c] * s2;
    float B2 = bn2[256 + c] - bn2[512 + c] * s2;
    __syncthreads();
    for (int o = tid; o < HO * HO; o += 256) {
        int oy = o / HO, ox = o - oy * HO;
        float acc = 0.f;
#pragma unroll
        for (int ky = 0; ky < K; ky++) {
            int iy = oy * S - P + ky;
            if (iy < 0 || iy > 63) continue;
#pragma unroll
            for (int kx = 0; kx < K; kx++) {
                int ix = ox * S - P + kx;
                if (ix >= 0 && ix <= 63) acc = fmaf(wk[ky * K + kx], xs[iy * 64 + ix], acc);
            }
        }
        float y1 = fmaxf(fmaf(acc, a1, c1), 0.f);
        ys[o] = fmaf(y1, A2, B2);
    }
    __syncthreads();
    float l9[9];
#pragma unroll
    for (int t = 0; t < 9; t++) l9[t] = lw[c * 9 + t];
    float lbv = lb[c];
    float *outp = (BR ? g_y3b : g_y3a) + (size_t)(b * 256 + c) * (HO * HO);
    for (int o = tid; o < HO * HO; o += 256) {
        int oy = o / HO, ox = o - oy * HO;
        float acc = lbv;
#pragma unroll
        for (int ky = 0; ky < 3; ky++) {
            int iy = oy - 1 + ky;
            if (iy < 0 || iy >= HO) continue;
#pragma unroll
            for (int kx = 0; kx < 3; kx++) {
                int ix = ox - 1 + kx;
                if (ix >= 0 && ix < HO) acc = fmaf(l9[ky * 3 + kx], ys[iy * HO + ix], acc);
            }
        }
        outp[o] = acc + ys[o];
    }
}

__global__ void __launch_bounds__(256) planes_k(const float * __restrict__ x,
                                                const float * __restrict__ dw1,
                                                const float * __restrict__ bn11,
                                                const float * __restrict__ pw1,
                                                const float * __restrict__ bn12,
                                                const float * __restrict__ dw2,
                                                const float * __restrict__ bn21,
                                                const float * __restrict__ pw2,
                                                const float * __restrict__ bn22,
                                                const float * __restrict__ lw,
                                                const float * __restrict__ lb) {
    __shared__ float xs[4096];
    __shared__ float ys[1024];
    __shared__ float wk[49];
    if (blockIdx.x < 512)
        plane_body<7, 4, 3, 16, 0>(blockIdx.x, x, dw1, bn11, pw1, bn12, lw, lb, xs, ys, wk);
    else
        plane_body<5, 2, 2, 32, 1>(blockIdx.x - 512, x, dw2, bn21, pw2, bn22, lw, lb, xs, ys, wk);
}

// -------- fp16 tensor-core flash attention (hi/lo split, 3-term both GEMMs) --------
// CTA = 128 thr = 4 warps sharing tiles; warp = 32 query rows.
// grid 2560: u<2048 br2 (8 chunks of 256 l); else br1 (2 chunks of 256 l).
__global__ void __launch_bounds__(128) attn_k() {
    int u = blockIdx.x;
    int b, h, br, ntile, chunk;
    if (u < 2048) { br = 1; b = u >> 10; int r = u & 1023; h = r >> 8;
                    int r2 = r & 255; ntile = r2 >> 3; chunk = r2 & 7; }
    else { int v = u - 2048; br = 0; b = v >> 8; int r = v & 255; h = r >> 6;
           int r2 = r & 63; ntile = r2 >> 1; chunk = r2 & 1; }
    int L = br ? 2048 : 512;
    const __half *Khp = br ? g_K2h : g_K1h;
    const __half *Klp = br ? g_K2l : g_K1l;
    const __half *Vhp = br ? g_V2h : g_V1h;
    const __half *Vlp = br ? g_V2l : g_V1l;
    const float *cr  = br ? g_cr2 : g_cr1;

    int tid = threadIdx.x, w = tid >> 5, lane = tid & 31;
    int g = lane >> 2, t = lane & 3;
    int n0 = ntile * 128;
    int n0w = n0 + w * 32;

    __shared__ __align__(16) __half KSH[2][16][40], KSL[2][16][40];
    __shared__ __align__(16) __half VSH[2][32][24], VSL[2][32][24];
    __shared__ __align__(16) float CRS[2][6][16];
    __shared__ u32 PSH[4][32][9], PSL[4][32][9];

    // q A-fragments (m16n8k16): pairs along d; hi/lo split; loop-invariant
    u32 qh2[2][2][4], ql2[2][2][4];
    const float *qbase = g_qT + (size_t)(b * 4 + h) * 4096 * 32;
#pragma unroll
    for (int mt = 0; mt < 2; mt++)
#pragma unroll
        for (int kt = 0; kt < 2; kt++) {
            int r0r = n0w + mt * 16 + g;
            int d0 = kt * 16 + 2 * t;
            const float *p0 = qbase + (size_t)r0r * 32;
            const float *p1 = qbase + (size_t)(r0r + 8) * 32;
            h2split(p0[d0],     p0[d0 + 1], qh2[mt][kt][0], ql2[mt][kt][0]);
            h2split(p1[d0],     p1[d0 + 1], qh2[mt][kt][1], ql2[mt][kt][1]);
            h2split(p0[d0 + 8], p0[d0 + 9], qh2[mt][kt][2], ql2[mt][kt][2]);
            h2split(p1[d0 + 8], p1[d0 + 9], qh2[mt][kt][3], ql2[mt][kt][3]);
        }

    // per-row bicubic weights (4 rows per thread: i = mt*2 + half)
    int r0 = g_rbase[n0];
    float wv[4][4]; int rr[4];
#pragma unroll
    for (int i = 0; i < 4; i++) {
        int ni = n0w + (i >> 1) * 16 + (i & 1) * 8 + g;
        rr[i] = g_rbase[ni] - r0;
#pragma unroll
        for (int j = 0; j < 4; j++) wv[i][j] = g_rw[ni * 4 + j];
    }

    size_t hbK = (size_t)(b * 4 + h) * L * 32;   // [l][32]
    size_t hbV = (size_t)(b * 4 + h) * 32 * L;   // [d][L]
    const float *crb = cr + (size_t)b * 64 * L;
    int l0base = chunk * 256;

    float of[2][4][4] = {};
    float m[4], sum[4];
#pragma unroll
    for (int i = 0; i < 4; i++) { m[i] = -1e30f; sum[i] = 0.f; }

    auto stage = [&](int buf, int l0) {
        if (tid < 64) {
            int row = tid >> 2, c = tid & 3;     // K: 16 rows x 4x16B
            size_t off = hbK + (size_t)(l0 + row) * 32 + c * 8;
            cpa16(&KSH[buf][row][c * 8], Khp + off);
            cpa16(&KSL[buf][row][c * 8], Klp + off);
        } else {
            int v = tid - 64, d = v >> 1, c = v & 1;  // Vt: 32 rows x 2x16B
            size_t off = hbV + (size_t)d * L + l0 + c * 8;
            cpa16(&VSH[buf][d][c * 8], Vhp + off);
            cpa16(&VSL[buf][d][c * 8], Vlp + off);
        }
        if (tid < 24) {
            int rrow = tid >> 2, c4 = tid & 3;
            int rc = r0 + rrow; if (rc > 63) rc = 63;
            cpa16(&CRS[buf][rrow][c4 * 4], crb + (size_t)rc * L + l0 + c4 * 4);
        }
        cpcommit();
    };

    stage(0, l0base);
    for (int ti = 0; ti < 16; ti++) {
        int cur = ti & 1;
        if (ti < 15) { stage(cur ^ 1, l0base + (ti + 1) * 16); cpwait1(); }
        else cpwait0();
        __syncthreads();

        // S accum seeded with rpe
        float sf[2][2][4];
#pragma unroll
        for (int i = 0; i < 4; i++) {
            int mt = i >> 1, hf = i & 1;
#pragma unroll
            for (int nt = 0; nt < 2; nt++)
#pragma unroll
                for (int d = 0; d < 2; d++) {
                    int col = nt * 8 + 2 * t + d;
                    float v = wv[i][0] * CRS[cur][rr[i]][col]
                            + wv[i][1] * CRS[cur][rr[i] + 1][col]
                            + wv[i][2] * CRS[cur][rr[i] + 2][col]
                            + wv[i][3] * CRS[cur][rr[i] + 3][col];
                    sf[mt][nt][hf * 2 + d] = v;
                }
        }
        // S = q @ K^T + rpe   (3-term: qh*kh + ql*kh + qh*kl)
#pragma unroll
        for (int nt = 0; nt < 2; nt++)
#pragma unroll
            for (int kt = 0; kt < 2; kt++) {
                int l = nt * 8 + g, d0 = kt * 16 + 2 * t;
                u32 b0h = *(const u32*)&KSH[cur][l][d0];
                u32 b1h = *(const u32*)&KSH[cur][l][d0 + 8];
                u32 b0l = *(const u32*)&KSL[cur][l][d0];
                u32 b1l = *(const u32*)&KSL[cur][l][d0 + 8];
                mma16(sf[0][nt], qh2[0][kt], b0h, b1h);
                mma16(sf[1][nt], qh2[1][kt], b0h, b1h);
                mma16(sf[0][nt], ql2[0][kt], b0h, b1h);
                mma16(sf[1][nt], ql2[1][kt], b0h, b1h);
                mma16(sf[0][nt], qh2[0][kt], b0l, b1l);
                mma16(sf[1][nt], qh2[1][kt], b0l, b1l);
            }
        // online softmax; pack P hi/lo half2 directly (pair l=2t,2t+1)
#pragma unroll
        for (int i = 0; i < 4; i++) {
            int mt = i >> 1, hf = i & 1;
            float a = fmaxf(fmaxf(sf[mt][0][2 * hf], sf[mt][0][2 * hf + 1]),
                            fmaxf(sf[mt][1][2 * hf], sf[mt][1][2 * hf + 1]));
            a = fmaxf(a, __shfl_xor_sync(0xffffffffu, a, 1));
            a = fmaxf(a, __shfl_xor_sync(0xffffffffu, a, 2));
            float nm = fmaxf(m[i], a);
            float f = ex2f(m[i] - nm);
            m[i] = nm; sum[i] *= f;
#pragma unroll
            for (int nt = 0; nt < 4; nt++) {
                of[mt][nt][2 * hf] *= f;
                of[mt][nt][2 * hf + 1] *= f;
            }
            int prow = mt * 16 + hf * 8 + g;
#pragma unroll
            for (int nt = 0; nt < 2; nt++) {
                float p0 = ex2f(sf[mt][nt][2 * hf]     - nm);
                float p1 = ex2f(sf[mt][nt][2 * hf + 1] - nm);
                sum[i] += p0 + p1;
                u32 hp, lp;
                h2split(p0, p1, hp, lp);
                PSH[w][prow][nt * 4 + t] = hp;
                PSL[w][prow][nt * 4 + t] = lp;
            }
        }
        __syncwarp();
        // O += P @ V   (3-term: ph*vh + pl*vh + ph*vl)
        u32 pah[2][4], pal[2][4];
#pragma unroll
        for (int mt = 0; mt < 2; mt++) {
            pah[mt][0] = PSH[w][mt * 16 + g][t];
            pah[mt][1] = PSH[w][mt * 16 + g + 8][t];
            pah[mt][2] = PSH[w][mt * 16 + g][t + 4];
            pah[mt][3] = PSH[w][mt * 16 + g + 8][t + 4];
            pal[mt][0] = PSL[w][mt * 16 + g][t];
            pal[mt][1] = PSL[w][mt * 16 + g + 8][t];
            pal[mt][2] = PSL[w][mt * 16 + g][t + 4];
            pal[mt][3] = PSL[w][mt * 16 + g + 8][t + 4];
        }
#pragma unroll
        for (int nt = 0; nt < 4; nt++) {
            int d = nt * 8 + g;
            u32 b0h = *(const u32*)&VSH[cur][d][2 * t];
            u32 b1h = *(const u32*)&VSH[cur][d][2 * t + 8];
            u32 b0l = *(const u32*)&VSL[cur][d][2 * t];
            u32 b1l = *(const u32*)&VSL[cur][d][2 * t + 8];
            mma16(of[0][nt], pah[0], b0h, b1h);
            mma16(of[1][nt], pah[1], b0h, b1h);
            mma16(of[0][nt], pal[0], b0h, b1h);
            mma16(of[1][nt], pal[1], b0h, b1h);
            mma16(of[0][nt], pah[0], b0l, b1l);
            mma16(of[1][nt], pah[1], b0l, b1l);
        }
        __syncthreads();   // anti-WAR: all warps done with buf `cur` before next prefetch
    }

    // epilogue: partials
    int nc = br ? 8 : 2;
    float *pO = br ? g_pO2 : g_pO1;
    float *pm = br ? g_pm2 : g_pm1;
    float *ps = br ? g_ps2 : g_ps1;
    size_t cb = (size_t)(b * 4 + h) * nc + chunk;
#pragma unroll
    for (int i = 0; i < 4; i++) {
        sum[i] += __shfl_xor_sync(0xffffffffu, sum[i], 1);
        sum[i] += __shfl_xor_sync(0xffffffffu, sum[i], 2);
    }
    if (t == 0) {
#pragma unroll
        for (int i = 0; i < 4; i++) {
            int ni = n0w + (i >> 1) * 16 + (i & 1) * 8 + g;
            pm[cb * 4096 + ni] = m[i];
            ps[cb * 4096 + ni] = sum[i];
        }
    }
#pragma unroll
    for (int mt = 0; mt < 2; mt++)
#pragma unroll
        for (int nt = 0; nt < 4; nt++)
#pragma unroll
            for (int k = 0; k < 4; k++) {
                int ni = n0w + mt * 16 + (k >> 1) * 8 + g;
                int d = nt * 8 + 2 * t + (k & 1);
                pO[((cb * 8 + (d >> 2)) * 4096 + ni) * 4 + (d & 3)] = of[mt][nt][k];
            }
}

// merge flash partials -> output (exp2 domain)
__global__ void __launch_bounds__(256) merge_k(float * __restrict__ out) {
    int idx = blockIdx.x * 256 + threadIdx.x;       // 65536
    int n = idx & 4095, h = (idx >> 12) & 3, br = (idx >> 14) & 1, b = idx >> 15;
    int nc = br ? 8 : 2;
    const float *pm = br ? g_pm2 : g_pm1;
    const float *ps = br ? g_ps2 : g_ps1;
    const float4 *pO = (const float4*)(br ? g_pO2 : g_pO1);
    size_t base = (size_t)(b * 4 + h) * nc;
    float M = -1e30f;
    for (int c = 0; c < nc; c++) M = fmaxf(M, pm[(base + c) * 4096 + n]);
    float S = 0.f;
    float4 acc[8] = {};
    for (int c = 0; c < nc; c++) {
        float w = ex2f(pm[(base + c) * 4096 + n] - M);
        S += w * ps[(base + c) * 4096 + n];
#pragma unroll
        for (int t = 0; t < 8; t++) {
            float4 v = pO[((base + c) * 8 + t) * 4096 + n];
            acc[t].x += w * v.x; acc[t].y += w * v.y;
            acc[t].z += w * v.z; acc[t].w += w * v.w;
        }
    }
    float inv = 1.f / S;
    int ny = n >> 6, nx = n & 63;
    float4 *op = (float4*)(out + ((((size_t)b * 256 + h * 64 + ny) * 64 + nx) * 64 + br * 32));
#pragma unroll
    for (int t = 0; t < 8; t++)
        op[t] = make_float4(acc[t].x * inv, acc[t].y * inv, acc[t].z * inv, acc[t].w * inv);
}

extern "C" void kernel_launch(void* const* d_in, const int* in_sizes, int n_in,
                              void* d_out, int out_size) {
    const float *x    = (const float*)d_in[0];
    const float *rpe  = (const float*)d_in[1];
    const float *q_w  = (const float*)d_in[2];
    const float *q_b  = (const float*)d_in[3];
    const float *kv_w = (const float*)d_in[4];
    const float *kv_b = (const float*)d_in[5];
    const float *dw1  = (const float*)d_in[6];
    const float *bn11 = (const float*)d_in[7];
    const float *pw1  = (const float*)d_in[8];
    const float *bn12 = (const float*)d_in[9];
    const float *dw2  = (const float*)d_in[10];
    const float *bn21 = (const float*)d_in[11];
    const float *pw2  = (const float*)d_in[12];
    const float *bn22 = (const float*)d_in[13];
    const float *lw   = (const float*)d_in[14];
    const float *lb   = (const float*)d_in[15];
    float *out = (float*)d_out;

    rowtab_k<<<16, 256>>>();
    colres_k<<<256, 256>>>(rpe, 512, 0);
    colres_k<<<1024, 256>>>(rpe, 2048, 1);
    planes_k<<<1024, 256>>>(x, dw1, bn11, pw1, bn12, dw2, bn21, pw2, bn22, lw, lb);
    gemm_k<<<1152, 128>>>(x, q_w, q_b, kv_w, kv_b);
    attn_k<<<2560, 128>>>();
    merge_k<<<256, 256>>>(out);
}